// round 3
// baseline (speedup 1.0000x reference)
#include <cuda_runtime.h>
#include <math.h>

typedef unsigned long long ull;

// Problem dims
#define S_   4096
#define T_   64
#define I_   64
#define EH_  128
#define E_   256
#define H_   512
#define O_   128
#define F1_  256
#define F2_  64
#define G4H_ (4*H_)       // 2048
#define KG_  (E_+H_)      // 768
#define ST_  (S_*T_)      // 262144

// ---------------- device scratch ----------------
__device__ float g_laneC;
__device__ float g_x1[(size_t)ST_ * EH_];     // 128 MB
__device__ float g_xemb[(size_t)ST_ * E_];    // 256 MB, layout [T][S][E]
__device__ float g_Wcomb[(size_t)G4H_ * KG_]; // interleaved [j*4+gate][768]
__device__ float g_bcomb[G4H_];
__device__ float g_h[(size_t)S_ * H_];
__device__ float g_hraw[(size_t)S_ * H_];
__device__ float g_c[(size_t)S_ * H_];
__device__ float g_o1[(size_t)S_ * O_];
__device__ float g_o2[(size_t)S_ * F1_];
__device__ float g_o3[(size_t)S_ * F2_];

// packed f32x2 helpers (sm_103a FFMA2 — PTX-only path)
#define FMA2(d, a, b) asm("fma.rn.f32x2 %0, %1, %2, %0;" : "+l"(d) : "l"(a), "l"(b))
#define PACK2(d, x)   asm("mov.b64 %0, {%1, %1};" : "=l"(d) : "f"(x))

__device__ __forceinline__ float2 unpk(ull v) {
    float2 r;
    asm("mov.b64 {%0, %1}, %2;" : "=f"(r.x), "=f"(r.y) : "l"(v));
    return r;
}

__device__ __forceinline__ float sigf(float x) {
    return __fdividef(1.0f, 1.0f + __expf(-x));
}
__device__ __forceinline__ float tanhf_(float x) {
    // 2*sigmoid(2x)-1 : saturates cleanly for |x| large
    return 2.0f * __fdividef(1.0f, 1.0f + __expf(-2.0f * x)) - 1.0f;
}

// ---------------- lane gate (scalar) ----------------
__global__ void lane_kernel(const float* __restrict__ lane,
                            const float* __restrict__ Wlg1,
                            const float* __restrict__ blg1,
                            const float* __restrict__ Wlg2,
                            const float* __restrict__ blg2) {
    int j = threadIdx.x;  // 32
    float lg = fmaxf(lane[0] * Wlg1[j] + blg1[j], 0.0f);
    float p = lg * Wlg2[j];
#pragma unroll
    for (int o = 16; o > 0; o >>= 1) p += __shfl_down_sync(0xFFFFFFFFu, p, o);
    if (j == 0) g_laneC = 1.0f / (1.0f + expf(-(p + blg2[0])));
}

// ---------------- weight interleave prep: row r=j*4+gate <- gate*512+j ----------------
__global__ void prep_weights(const float* __restrict__ Wih,  // [2048,256]
                             const float* __restrict__ Whh,  // [2048,512]
                             const float* __restrict__ bih,
                             const float* __restrict__ bhh) {
    int r = blockIdx.x;                 // 0..2047 interleaved row
    int orig = (r & 3) * H_ + (r >> 2); // original torch row
    float* dst = g_Wcomb + (size_t)r * KG_;
    for (int k = threadIdx.x; k < KG_; k += blockDim.x)
        dst[k] = (k < E_) ? Wih[(size_t)orig * E_ + k]
                          : Whh[(size_t)orig * H_ + (k - E_)];
    if (threadIdx.x == 0) g_bcomb[r] = bih[orig] + bhh[orig];
}

// ---------------- generic FFMA2 SGEMM: C = act(A @ B^T + bias) ----------------
#define BM 128
#define BN 128
#define BK 8
#define FL_RELU    1
#define FL_SCALEA  2
#define FL_PERMT   4

__global__ __launch_bounds__(256, 2)
void sgemm2(int M, int N, int K,
            const float* __restrict__ A, int lda,
            const float* __restrict__ B,
            const float* __restrict__ bias,
            float* __restrict__ C, int ldc, int flags)
{
    __shared__ __align__(16) float As[BK][BM];
    __shared__ __align__(16) float Bs[BK][BN];

    const int tid = threadIdx.x;
    const int tx = tid & 15;
    const int ty = tid >> 4;
    const int bm = blockIdx.y * BM;
    const int bn = blockIdx.x * BN;
    const float scale = (flags & FL_SCALEA) ? g_laneC : 1.0f;
    const int lRow = tid >> 1;
    const int lCol = (tid & 1) * 4;

    ull acc[8][4];
#pragma unroll
    for (int i = 0; i < 8; i++)
#pragma unroll
        for (int p = 0; p < 4; p++) acc[i][p] = 0ull;

    for (int k0 = 0; k0 < K; k0 += BK) {
        float4 av = make_float4(0.f, 0.f, 0.f, 0.f);
        int ar = bm + lRow;
        if (ar < M) av = *reinterpret_cast<const float4*>(A + (size_t)ar * lda + (k0 + lCol));
        As[lCol + 0][lRow] = av.x * scale;
        As[lCol + 1][lRow] = av.y * scale;
        As[lCol + 2][lRow] = av.z * scale;
        As[lCol + 3][lRow] = av.w * scale;

        float4 bv = make_float4(0.f, 0.f, 0.f, 0.f);
        int br = bn + lRow;
        if (br < N) bv = *reinterpret_cast<const float4*>(B + (size_t)br * K + (k0 + lCol));
        Bs[lCol + 0][lRow] = bv.x;
        Bs[lCol + 1][lRow] = bv.y;
        Bs[lCol + 2][lRow] = bv.z;
        Bs[lCol + 3][lRow] = bv.w;

        __syncthreads();

#pragma unroll
        for (int k = 0; k < BK; k++) {
            float4 a0 = *reinterpret_cast<const float4*>(&As[k][ty * 4]);
            float4 a1 = *reinterpret_cast<const float4*>(&As[k][64 + ty * 4]);
            const ull* bp0 = reinterpret_cast<const ull*>(&Bs[k][tx * 4]);
            const ull* bp1 = reinterpret_cast<const ull*>(&Bs[k][64 + tx * 4]);
            ull b0 = bp0[0], b1 = bp0[1], b2 = bp1[0], b3 = bp1[1];
            float as[8] = {a0.x, a0.y, a0.z, a0.w, a1.x, a1.y, a1.z, a1.w};
            ull aa;
#pragma unroll
            for (int i = 0; i < 8; i++) {
                PACK2(aa, as[i]);
                FMA2(acc[i][0], aa, b0);
                FMA2(acc[i][1], aa, b1);
                FMA2(acc[i][2], aa, b2);
                FMA2(acc[i][3], aa, b3);
            }
        }
        __syncthreads();
    }

#pragma unroll
    for (int i = 0; i < 8; i++) {
        int row = bm + ((i < 4) ? (ty * 4 + i) : (64 + ty * 4 + (i - 4)));
        if (row >= M) continue;
        size_t orow = (flags & FL_PERMT)
                      ? ((size_t)(row % T_) * S_ + (row / T_))
                      : (size_t)row;
#pragma unroll
        for (int p = 0; p < 4; p++) {
            float2 v = unpk(acc[i][p]);
            int c0 = bn + ((p < 2) ? (tx * 4 + p * 2) : (64 + tx * 4 + (p - 2) * 2));
#pragma unroll
            for (int q = 0; q < 2; q++) {
                int col = c0 + q;
                if (col >= N) continue;
                float val = (q == 0) ? v.x : v.y;
                if (bias) val += bias[col];
                if (flags & FL_RELU) val = fmaxf(val, 0.0f);
                C[orow * ldc + col] = val;
            }
        }
    }
}

// ------------- per-step gates GEMM + fused LSTM cell -------------
// gates = [xemb_t, h] @ Wcomb^T + bcomb (interleaved cols: j*4 + {i,f,g,o})
// epilogue computes c,hraw directly.
__global__ __launch_bounds__(256, 2)
void gates_cell_gemm(int t)
{
    __shared__ __align__(16) float As[BK][BM];
    __shared__ __align__(16) float Bs[BK][BN];

    const int tid = threadIdx.x;
    const int tx = tid & 15;
    const int ty = tid >> 4;
    const int bm = blockIdx.y * BM;
    const int bn = blockIdx.x * BN;
    const int lRow = tid >> 1;
    const int lCol = (tid & 1) * 4;

    ull acc[8][4];
#pragma unroll
    for (int i = 0; i < 8; i++)
#pragma unroll
        for (int p = 0; p < 4; p++) acc[i][p] = 0ull;

    const float* xslice = g_xemb + (size_t)t * S_ * E_;

    for (int k0 = 0; k0 < KG_; k0 += BK) {
        int ar = bm + lRow;
        const float* aptr = (k0 < E_)
            ? xslice + (size_t)ar * E_ + (k0 + lCol)
            : g_h + (size_t)ar * H_ + (k0 - E_ + lCol);
        float4 av = *reinterpret_cast<const float4*>(aptr);
        As[lCol + 0][lRow] = av.x;
        As[lCol + 1][lRow] = av.y;
        As[lCol + 2][lRow] = av.z;
        As[lCol + 3][lRow] = av.w;

        int br = bn + lRow;
        float4 bv = *reinterpret_cast<const float4*>(g_Wcomb + (size_t)br * KG_ + (k0 + lCol));
        Bs[lCol + 0][lRow] = bv.x;
        Bs[lCol + 1][lRow] = bv.y;
        Bs[lCol + 2][lRow] = bv.z;
        Bs[lCol + 3][lRow] = bv.w;

        __syncthreads();

#pragma unroll
        for (int k = 0; k < BK; k++) {
            float4 a0 = *reinterpret_cast<const float4*>(&As[k][ty * 4]);
            float4 a1 = *reinterpret_cast<const float4*>(&As[k][64 + ty * 4]);
            const ull* bp0 = reinterpret_cast<const ull*>(&Bs[k][tx * 4]);
            const ull* bp1 = reinterpret_cast<const ull*>(&Bs[k][64 + tx * 4]);
            ull b0 = bp0[0], b1 = bp0[1], b2 = bp1[0], b3 = bp1[1];
            float as[8] = {a0.x, a0.y, a0.z, a0.w, a1.x, a1.y, a1.z, a1.w};
            ull aa;
#pragma unroll
            for (int i = 0; i < 8; i++) {
                PACK2(aa, as[i]);
                FMA2(acc[i][0], aa, b0);
                FMA2(acc[i][1], aa, b1);
                FMA2(acc[i][2], aa, b2);
                FMA2(acc[i][3], aa, b3);
            }
        }
        __syncthreads();
    }

    // bias for this thread's 8 cols (two gate-units)
    float4 bA = *reinterpret_cast<const float4*>(&g_bcomb[bn + tx * 4]);
    float4 bB = *reinterpret_cast<const float4*>(&g_bcomb[bn + 64 + tx * 4]);
    int unitA = (bn >> 2) + tx;        // h-index for group A
    int unitB = (bn >> 2) + 16 + tx;   // h-index for group B

#pragma unroll
    for (int i = 0; i < 8; i++) {
        int s = bm + ((i < 4) ? (ty * 4 + i) : (64 + ty * 4 + (i - 4)));
        // group A: pairs 0 (i,f), 1 (g,o)
        {
            float2 p0 = unpk(acc[i][0]);
            float2 p1 = unpk(acc[i][1]);
            float ig = sigf(p0.x + bA.x);
            float fg = sigf(p0.y + bA.y);
            float gg = tanhf_(p1.x + bA.z);
            float og = sigf(p1.y + bA.w);
            size_t idx = (size_t)s * H_ + unitA;
            float cn = fg * g_c[idx] + ig * gg;
            g_c[idx] = cn;
            g_hraw[idx] = og * tanhf_(cn);
        }
        // group B: pairs 2 (i,f), 3 (g,o)
        {
            float2 p0 = unpk(acc[i][2]);
            float2 p1 = unpk(acc[i][3]);
            float ig = sigf(p0.x + bB.x);
            float fg = sigf(p0.y + bB.y);
            float gg = tanhf_(p1.x + bB.z);
            float og = sigf(p1.y + bB.w);
            size_t idx = (size_t)s * H_ + unitB;
            float cn = fg * g_c[idx] + ig * gg;
            g_c[idx] = cn;
            g_hraw[idx] = og * tanhf_(cn);
        }
    }
}

// ---------------- spatial maxpool (k=3, s=1, p=1, -inf pad) ----------------
__global__ void maxpool_kernel() {
    int idx = blockIdx.x * blockDim.x + threadIdx.x;
    if (idx >= S_ * H_) return;
    int s = idx >> 9;
    float v = g_hraw[idx];
    if (s > 0)       v = fmaxf(v, g_hraw[idx - H_]);
    if (s < S_ - 1)  v = fmaxf(v, g_hraw[idx + H_]);
    g_h[idx] = v;
}

__global__ void zero_hc_kernel() {
    int idx = blockIdx.x * blockDim.x + threadIdx.x;
    if (idx >= S_ * H_) return;
    g_h[idx] = 0.0f;
    g_c[idx] = 0.0f;
}

// ---------------- final head: out[s] = (o3[s,:] . Wf3 + bf3) / laneC ----------------
__global__ void head_final_kernel(const float* __restrict__ Wf3,
                                  const float* __restrict__ bf3,
                                  float* __restrict__ out) {
    __shared__ float red[F2_];
    int s = blockIdx.x;
    int t = threadIdx.x;  // 64
    red[t] = g_o3[(size_t)s * F2_ + t] * Wf3[t];
    __syncthreads();
#pragma unroll
    for (int o = 32; o > 0; o >>= 1) {
        if (t < o) red[t] += red[t + o];
        __syncthreads();
    }
    if (t == 0) out[s] = (red[0] + bf3[0]) / g_laneC;
}

// ---------------- copy h, c into d_out ----------------
__global__ void finalize_kernel(float* __restrict__ out) {
    int idx = blockIdx.x * blockDim.x + threadIdx.x;
    if (idx >= S_ * H_) return;
    out[S_ + idx] = g_h[idx];
    out[S_ + (size_t)S_ * H_ + idx] = g_c[idx];
}

// ---------------- host launcher ----------------
extern "C" void kernel_launch(void* const* d_in, const int* in_sizes, int n_in,
                              void* d_out, int out_size) {
    const float* inputData = (const float*)d_in[0];
    const float* lane      = (const float*)d_in[1];
    const float* Wlg1      = (const float*)d_in[2];
    const float* blg1      = (const float*)d_in[3];
    const float* Wlg2      = (const float*)d_in[4];
    const float* blg2      = (const float*)d_in[5];
    const float* We1       = (const float*)d_in[6];
    const float* be1       = (const float*)d_in[7];
    const float* We2       = (const float*)d_in[8];
    const float* be2       = (const float*)d_in[9];
    const float* Wih       = (const float*)d_in[10];
    const float* bih       = (const float*)d_in[11];
    const float* Whh       = (const float*)d_in[12];
    const float* bhh       = (const float*)d_in[13];
    const float* Wout      = (const float*)d_in[14];
    const float* bout      = (const float*)d_in[15];
    const float* Wf1       = (const float*)d_in[16];
    const float* bf1       = (const float*)d_in[17];
    const float* Wf2       = (const float*)d_in[18];
    const float* bf2       = (const float*)d_in[19];
    const float* Wf3       = (const float*)d_in[20];
    const float* bf3       = (const float*)d_in[21];
    float* out = (float*)d_out;

    float *p_x1, *p_xemb, *p_h, *p_o1, *p_o2, *p_o3;
    cudaGetSymbolAddress((void**)&p_x1,   g_x1);
    cudaGetSymbolAddress((void**)&p_xemb, g_xemb);
    cudaGetSymbolAddress((void**)&p_h,    g_h);
    cudaGetSymbolAddress((void**)&p_o1,   g_o1);
    cudaGetSymbolAddress((void**)&p_o2,   g_o2);
    cudaGetSymbolAddress((void**)&p_o3,   g_o3);

    dim3 blk(256);

    // weight interleave + lane gate
    prep_weights<<<G4H_, 256>>>(Wih, Whh, bih, bhh);
    lane_kernel<<<1, 32>>>(lane, Wlg1, blg1, Wlg2, blg2);

    // embedding MLP; second GEMM permutes output to [T][S][E]
    sgemm2<<<dim3(EH_ / BN, ST_ / BM), blk>>>(ST_, EH_, I_, inputData, I_, We1, be1,
                                              p_x1, EH_, FL_RELU | FL_SCALEA);
    sgemm2<<<dim3(E_ / BN, ST_ / BM), blk>>>(ST_, E_, EH_, p_x1, EH_, We2, be2,
                                             p_xemb, E_, FL_RELU | FL_PERMT);

    int ew = S_ * H_;
    zero_hc_kernel<<<(ew + 255) / 256, 256>>>();

    // recurrence: fused GEMM+cell, then maxpool
    dim3 ggrid(G4H_ / BN, S_ / BM);  // 16 x 32
    for (int t = 0; t < T_; t++) {
        gates_cell_gemm<<<ggrid, blk>>>(t);
        maxpool_kernel<<<(ew + 255) / 256, 256>>>();
    }

    // output head
    sgemm2<<<dim3(O_ / BN, S_ / BM), blk>>>(S_, O_, H_, p_h, H_, Wout, bout,
                                            p_o1, O_, 0);
    sgemm2<<<dim3((F1_ + BN - 1) / BN, S_ / BM), blk>>>(S_, F1_, O_, p_o1, O_, Wf1, bf1,
                                                        p_o2, F1_, FL_RELU);
    sgemm2<<<dim3((F2_ + BN - 1) / BN, S_ / BM), blk>>>(S_, F2_, F1_, p_o2, F1_, Wf2, bf2,
                                                        p_o3, F2_, FL_RELU);
    head_final_kernel<<<S_, F2_>>>(Wf3, bf3, out);
    finalize_kernel<<<(ew + 255) / 256, 256>>>(out);
}

// round 5
// speedup vs baseline: 2.0225x; 2.0225x over previous
#include <cuda_runtime.h>
#include <cuda_bf16.h>
#include <math.h>
#include <cstdint>

typedef unsigned long long ull;

// Problem dims
#define S_   4096
#define T_   64
#define I_   64
#define EH_  128
#define E_   256
#define H_   512
#define O_   128
#define F1_  256
#define F2_  64
#define G4H_ (4*H_)       // 2048
#define KG_  (E_+H_)      // 768
#define ST_  (S_*T_)      // 262144

// ---------------- device scratch ----------------
__device__ float g_laneC;
__device__ float g_x1[(size_t)ST_ * EH_];               // 128 MB
__device__ __nv_bfloat16 g_xemb_hi[(size_t)ST_ * E_];   // [T][S][E] bf16 hi
__device__ __nv_bfloat16 g_xemb_lo[(size_t)ST_ * E_];   // [T][S][E] bf16 lo
__device__ __nv_bfloat16 g_Whi[(size_t)G4H_ * KG_];     // interleaved rows j*4+gate
__device__ __nv_bfloat16 g_Wlo[(size_t)G4H_ * KG_];
__device__ float g_bcomb[G4H_];
__device__ float g_h[(size_t)S_ * H_];
__device__ __nv_bfloat16 g_hhi[(size_t)S_ * H_];
__device__ __nv_bfloat16 g_hlo[(size_t)S_ * H_];
__device__ float g_hraw[(size_t)S_ * H_];
__device__ float g_c[(size_t)S_ * H_];
__device__ float g_o1[(size_t)S_ * O_];
__device__ float g_o2[(size_t)S_ * F1_];
__device__ float g_o3[(size_t)S_ * F2_];

// ---------------- helpers ----------------
__device__ __forceinline__ uint32_t smem_u32(const void* p) {
    uint32_t a;
    asm("{ .reg .u64 t; cvta.to.shared.u64 t, %1; cvt.u32.u64 %0, t; }" : "=r"(a) : "l"(p));
    return a;
}
#define CP16(dst, src) asm volatile("cp.async.cg.shared.global [%0], [%1], 16;" :: "r"(dst), "l"(src))
#define CP_COMMIT()    asm volatile("cp.async.commit_group;" ::: "memory")
#define CP_WAIT1()     asm volatile("cp.async.wait_group 1;" ::: "memory")
#define CP_WAIT0()     asm volatile("cp.async.wait_group 0;" ::: "memory")

#define MMA16816(c, a, b) \
    asm volatile("mma.sync.aligned.m16n8k16.row.col.f32.bf16.bf16.f32 " \
        "{%0,%1,%2,%3}, {%4,%5,%6,%7}, {%8,%9}, {%0,%1,%2,%3};" \
        : "+f"((c)[0]), "+f"((c)[1]), "+f"((c)[2]), "+f"((c)[3]) \
        : "r"((a)[0]), "r"((a)[1]), "r"((a)[2]), "r"((a)[3]), \
          "r"((b)[0]), "r"((b)[1]))

// packed f32x2 helpers for scalar GEMMs
#define FMA2(d, a, b) asm("fma.rn.f32x2 %0, %1, %2, %0;" : "+l"(d) : "l"(a), "l"(b))
#define PACK2(d, x)   asm("mov.b64 %0, {%1, %1};" : "=l"(d) : "f"(x))
__device__ __forceinline__ float2 unpk(ull v) {
    float2 r;
    asm("mov.b64 {%0, %1}, %2;" : "=f"(r.x), "=f"(r.y) : "l"(v));
    return r;
}
__device__ __forceinline__ float sigf(float x) { return __fdividef(1.0f, 1.0f + __expf(-x)); }
__device__ __forceinline__ float tanhf_(float x) {
    return 2.0f * __fdividef(1.0f, 1.0f + __expf(-2.0f * x)) - 1.0f;
}

// ---------------- lane gate ----------------
__global__ void lane_kernel(const float* __restrict__ lane,
                            const float* __restrict__ Wlg1,
                            const float* __restrict__ blg1,
                            const float* __restrict__ Wlg2,
                            const float* __restrict__ blg2) {
    int j = threadIdx.x;
    float lg = fmaxf(lane[0] * Wlg1[j] + blg1[j], 0.0f);
    float p = lg * Wlg2[j];
#pragma unroll
    for (int o = 16; o > 0; o >>= 1) p += __shfl_down_sync(0xFFFFFFFFu, p, o);
    if (j == 0) g_laneC = 1.0f / (1.0f + expf(-(p + blg2[0])));
}

// ---------------- weight interleave + bf16 split ----------------
__global__ void prep_weights(const float* __restrict__ Wih,
                             const float* __restrict__ Whh,
                             const float* __restrict__ bih,
                             const float* __restrict__ bhh) {
    int r = blockIdx.x;                 // interleaved row: j*4 + gate
    int orig = (r & 3) * H_ + (r >> 2);
    for (int k = threadIdx.x; k < KG_; k += blockDim.x) {
        float w = (k < E_) ? Wih[(size_t)orig * E_ + k] : Whh[(size_t)orig * H_ + (k - E_)];
        __nv_bfloat16 hi = __float2bfloat16(w);
        g_Whi[(size_t)r * KG_ + k] = hi;
        g_Wlo[(size_t)r * KG_ + k] = __float2bfloat16(w - __bfloat162float(hi));
    }
    if (threadIdx.x == 0) g_bcomb[r] = bih[orig] + bhh[orig];
}

// ---------------- scalar FFMA2 SGEMM (embedding + head) ----------------
#define BM 128
#define BN 128
#define BK 8
#define FL_RELU    1
#define FL_SCALEA  2
#define FL_SPLIT   4   // write bf16 hi/lo to g_xemb_* with [T][S][E] permute

__global__ __launch_bounds__(256, 2)
void sgemm2(int M, int N, int K,
            const float* __restrict__ A, int lda,
            const float* __restrict__ B,
            const float* __restrict__ bias,
            float* __restrict__ C, int ldc, int flags)
{
    __shared__ __align__(16) float As[BK][BM];
    __shared__ __align__(16) float Bs[BK][BN];

    const int tid = threadIdx.x;
    const int tx = tid & 15;
    const int ty = tid >> 4;
    const int bm = blockIdx.y * BM;
    const int bn = blockIdx.x * BN;
    const float scale = (flags & FL_SCALEA) ? g_laneC : 1.0f;
    const int lRow = tid >> 1;
    const int lCol = (tid & 1) * 4;

    ull acc[8][4];
#pragma unroll
    for (int i = 0; i < 8; i++)
#pragma unroll
        for (int p = 0; p < 4; p++) acc[i][p] = 0ull;

    for (int k0 = 0; k0 < K; k0 += BK) {
        float4 av = make_float4(0.f, 0.f, 0.f, 0.f);
        int ar = bm + lRow;
        if (ar < M) av = *reinterpret_cast<const float4*>(A + (size_t)ar * lda + (k0 + lCol));
        As[lCol + 0][lRow] = av.x * scale;
        As[lCol + 1][lRow] = av.y * scale;
        As[lCol + 2][lRow] = av.z * scale;
        As[lCol + 3][lRow] = av.w * scale;

        float4 bv = make_float4(0.f, 0.f, 0.f, 0.f);
        int br = bn + lRow;
        if (br < N) bv = *reinterpret_cast<const float4*>(B + (size_t)br * K + (k0 + lCol));
        Bs[lCol + 0][lRow] = bv.x;
        Bs[lCol + 1][lRow] = bv.y;
        Bs[lCol + 2][lRow] = bv.z;
        Bs[lCol + 3][lRow] = bv.w;

        __syncthreads();
#pragma unroll
        for (int k = 0; k < BK; k++) {
            float4 a0 = *reinterpret_cast<const float4*>(&As[k][ty * 4]);
            float4 a1 = *reinterpret_cast<const float4*>(&As[k][64 + ty * 4]);
            const ull* bp0 = reinterpret_cast<const ull*>(&Bs[k][tx * 4]);
            const ull* bp1 = reinterpret_cast<const ull*>(&Bs[k][64 + tx * 4]);
            ull b0 = bp0[0], b1 = bp0[1], b2 = bp1[0], b3 = bp1[1];
            float as[8] = {a0.x, a0.y, a0.z, a0.w, a1.x, a1.y, a1.z, a1.w};
            ull aa;
#pragma unroll
            for (int i = 0; i < 8; i++) {
                PACK2(aa, as[i]);
                FMA2(acc[i][0], aa, b0);
                FMA2(acc[i][1], aa, b1);
                FMA2(acc[i][2], aa, b2);
                FMA2(acc[i][3], aa, b3);
            }
        }
        __syncthreads();
    }

#pragma unroll
    for (int i = 0; i < 8; i++) {
        int row = bm + ((i < 4) ? (ty * 4 + i) : (64 + ty * 4 + (i - 4)));
        if (row >= M) continue;
        size_t orow = (flags & FL_SPLIT)
                      ? ((size_t)(row % T_) * S_ + (row / T_))
                      : (size_t)row;
#pragma unroll
        for (int p = 0; p < 4; p++) {
            float2 v = unpk(acc[i][p]);
            int c0 = bn + ((p < 2) ? (tx * 4 + p * 2) : (64 + tx * 4 + (p - 2) * 2));
#pragma unroll
            for (int q = 0; q < 2; q++) {
                int col = c0 + q;
                if (col >= N) continue;
                float val = (q == 0) ? v.x : v.y;
                if (bias) val += bias[col];
                if (flags & FL_RELU) val = fmaxf(val, 0.0f);
                if (flags & FL_SPLIT) {
                    __nv_bfloat16 hi = __float2bfloat16(val);
                    g_xemb_hi[orow * ldc + col] = hi;
                    g_xemb_lo[orow * ldc + col] = __float2bfloat16(val - __bfloat162float(hi));
                } else {
                    C[orow * ldc + col] = val;
                }
            }
        }
    }
}

// ============ mma.sync bf16 gates GEMM (K-extended 3-term split) + fused cell ============
// D[s, gatecol] = sum over K'=2304:  [A_hi|A_lo|A_hi] . [W_hi|W_hi|W_lo]
// CTA tile 128x128, BK=64, 4 warps (64x64 warp tiles), cp.async double buffer.
#define GBK 64
#define NCH 36                 // 2304 / 64
#define KPAD 72                // 64 + 8 halves padding (row stride 144 B)
#define A_BYTES (128 * KPAD * 2)   // 18432
#define STAGE_B (2 * A_BYTES)      // A + B per stage = 36864
#define SM_TOT  (2 * STAGE_B)      // 73728 (>= 128*132*4 epilogue staging)

__global__ __launch_bounds__(128)
void gates_mma(int t)
{
    extern __shared__ char smem[];
    const uint32_t sb = smem_u32(smem);
    const int tid = threadIdx.x;
    const int lane = tid & 31;
    const int wid = tid >> 5;
    const int wm = wid & 1;        // warp row (2)
    const int wn = wid >> 1;       // warp col (2)
    const int bm = blockIdx.y * 128;
    const int bn = blockIdx.x * 128;

    float acc[4][8][4];
#pragma unroll
    for (int mf = 0; mf < 4; mf++)
#pragma unroll
        for (int nf = 0; nf < 8; nf++)
#pragma unroll
            for (int r = 0; r < 4; r++) acc[mf][nf][r] = 0.0f;

    auto load_chunk = [&](int ck, int st) {
        const int seg = ck / 12;          // 0: hi.hi  1: lo.hi  2: hi.lo
        const int kk = (ck % 12) * GBK;   // 0..704
        const __nv_bfloat16* asrc;
        size_t astr;
        if (kk < E_) {
            asrc = ((seg == 1) ? g_xemb_lo : g_xemb_hi) + ((size_t)t * S_ + bm) * E_ + kk;
            astr = E_;
        } else {
            asrc = ((seg == 1) ? g_hlo : g_hhi) + (size_t)bm * H_ + (kk - E_);
            astr = H_;
        }
        const __nv_bfloat16* bsrc = ((seg == 2) ? g_Wlo : g_Whi) + (size_t)bn * KG_ + kk;
        const uint32_t abase = sb + (uint32_t)(st * STAGE_B);
        const uint32_t bbase = abase + A_BYTES;
#pragma unroll
        for (int it = 0; it < 8; it++) {
            int i = tid + it * 128;
            int row = i >> 3, sg = i & 7;
            CP16(abase + row * 144 + sg * 16, asrc + (size_t)row * astr + sg * 8);
        }
#pragma unroll
        for (int it = 0; it < 8; it++) {
            int i = tid + it * 128;
            int row = i >> 3, sg = i & 7;
            CP16(bbase + row * 144 + sg * 16, bsrc + (size_t)row * KG_ + sg * 8);
        }
    };

    load_chunk(0, 0);
    CP_COMMIT();

    for (int ck = 0; ck < NCH; ck++) {
        const int st = ck & 1;
        if (ck + 1 < NCH) {
            load_chunk(ck + 1, st ^ 1);
            CP_COMMIT();
            CP_WAIT1();
        } else {
            CP_WAIT0();
        }
        __syncthreads();

        const uint32_t* As32 = reinterpret_cast<const uint32_t*>(smem + st * STAGE_B);
        const uint32_t* Bs32 = reinterpret_cast<const uint32_t*>(smem + st * STAGE_B + A_BYTES);
#pragma unroll
        for (int kh = 0; kh < 4; kh++) {
            uint32_t af[4][4];
#pragma unroll
            for (int mf = 0; mf < 4; mf++) {
                int r0 = wm * 64 + mf * 16 + (lane >> 2);
                int c = kh * 8 + (lane & 3);
                af[mf][0] = As32[r0 * 36 + c];
                af[mf][1] = As32[(r0 + 8) * 36 + c];
                af[mf][2] = As32[r0 * 36 + c + 4];
                af[mf][3] = As32[(r0 + 8) * 36 + c + 4];
            }
            uint32_t bfr[8][2];
#pragma unroll
            for (int nf = 0; nf < 8; nf++) {
                int n0 = wn * 64 + nf * 8 + (lane >> 2);
                int c = kh * 8 + (lane & 3);
                bfr[nf][0] = Bs32[n0 * 36 + c];
                bfr[nf][1] = Bs32[n0 * 36 + c + 4];
            }
#pragma unroll
            for (int mf = 0; mf < 4; mf++)
#pragma unroll
                for (int nf = 0; nf < 8; nf++)
                    MMA16816(acc[mf][nf], af[mf], bfr[nf]);
        }
        __syncthreads();
    }

    // ---- epilogue: stage accum to smem, then fused LSTM cell ----
    float* Sg = reinterpret_cast<float*>(smem);  // [128][132]
#pragma unroll
    for (int mf = 0; mf < 4; mf++) {
        int r0 = wm * 64 + mf * 16 + (lane >> 2);
#pragma unroll
        for (int nf = 0; nf < 8; nf++) {
            int col = wn * 64 + nf * 8 + (lane & 3) * 2;
            *reinterpret_cast<float2*>(&Sg[r0 * 132 + col]) =
                make_float2(acc[mf][nf][0], acc[mf][nf][1]);
            *reinterpret_cast<float2*>(&Sg[(r0 + 8) * 132 + col]) =
                make_float2(acc[mf][nf][2], acc[mf][nf][3]);
        }
    }
    __syncthreads();

    const int jbase = bn >> 2;   // first h-unit of this tile
#pragma unroll 4
    for (int it = 0; it < 32; it++) {
        int idx = tid + it * 128;
        int row = idx >> 5, u = idx & 31;
        float4 gv = *reinterpret_cast<const float4*>(&Sg[row * 132 + u * 4]);
        float4 bb = *reinterpret_cast<const float4*>(&g_bcomb[bn + u * 4]);
        size_t cidx = (size_t)(bm + row) * H_ + (jbase + u);
        float cn = sigf(gv.y + bb.y) * g_c[cidx] + sigf(gv.x + bb.x) * tanhf_(gv.z + bb.z);
        g_c[cidx] = cn;
        g_hraw[cidx] = sigf(gv.w + bb.w) * tanhf_(cn);
    }
}

// ---------------- spatial maxpool + bf16 split of h ----------------
__global__ void maxpool_kernel() {
    int idx = blockIdx.x * blockDim.x + threadIdx.x;
    if (idx >= S_ * H_) return;
    int s = idx >> 9;
    float v = g_hraw[idx];
    if (s > 0)       v = fmaxf(v, g_hraw[idx - H_]);
    if (s < S_ - 1)  v = fmaxf(v, g_hraw[idx + H_]);
    g_h[idx] = v;
    __nv_bfloat16 hi = __float2bfloat16(v);
    g_hhi[idx] = hi;
    g_hlo[idx] = __float2bfloat16(v - __bfloat162float(hi));
}

__global__ void zero_hc_kernel() {
    int idx = blockIdx.x * blockDim.x + threadIdx.x;
    if (idx >= S_ * H_) return;
    g_h[idx] = 0.0f;
    g_c[idx] = 0.0f;
    g_hhi[idx] = __float2bfloat16(0.0f);
    g_hlo[idx] = __float2bfloat16(0.0f);
}

// ---------------- final head ----------------
__global__ void head_final_kernel(const float* __restrict__ Wf3,
                                  const float* __restrict__ bf3,
                                  float* __restrict__ out) {
    __shared__ float red[F2_];
    int s = blockIdx.x;
    int t = threadIdx.x;
    red[t] = g_o3[(size_t)s * F2_ + t] * Wf3[t];
    __syncthreads();
#pragma unroll
    for (int o = 32; o > 0; o >>= 1) {
        if (t < o) red[t] += red[t + o];
        __syncthreads();
    }
    if (t == 0) out[s] = (red[0] + bf3[0]) / g_laneC;
}

__global__ void finalize_kernel(float* __restrict__ out) {
    int idx = blockIdx.x * blockDim.x + threadIdx.x;
    if (idx >= S_ * H_) return;
    out[S_ + idx] = g_h[idx];
    out[S_ + (size_t)S_ * H_ + idx] = g_c[idx];
}

// ---------------- host launcher ----------------
extern "C" void kernel_launch(void* const* d_in, const int* in_sizes, int n_in,
                              void* d_out, int out_size) {
    const float* inputData = (const float*)d_in[0];
    const float* lane      = (const float*)d_in[1];
    const float* Wlg1      = (const float*)d_in[2];
    const float* blg1      = (const float*)d_in[3];
    const float* Wlg2      = (const float*)d_in[4];
    const float* blg2      = (const float*)d_in[5];
    const float* We1       = (const float*)d_in[6];
    const float* be1       = (const float*)d_in[7];
    const float* We2       = (const float*)d_in[8];
    const float* be2       = (const float*)d_in[9];
    const float* Wih       = (const float*)d_in[10];
    const float* bih       = (const float*)d_in[11];
    const float* Whh       = (const float*)d_in[12];
    const float* bhh       = (const float*)d_in[13];
    const float* Wout      = (const float*)d_in[14];
    const float* bout      = (const float*)d_in[15];
    const float* Wf1       = (const float*)d_in[16];
    const float* bf1       = (const float*)d_in[17];
    const float* Wf2       = (const float*)d_in[18];
    const float* bf2       = (const float*)d_in[19];
    const float* Wf3       = (const float*)d_in[20];
    const float* bf3       = (const float*)d_in[21];
    float* out = (float*)d_out;

    float *p_x1, *p_h, *p_o1, *p_o2, *p_o3;
    cudaGetSymbolAddress((void**)&p_x1, g_x1);
    cudaGetSymbolAddress((void**)&p_h,  g_h);
    cudaGetSymbolAddress((void**)&p_o1, g_o1);
    cudaGetSymbolAddress((void**)&p_o2, g_o2);
    cudaGetSymbolAddress((void**)&p_o3, g_o3);

    static int smem_set = 0;
    if (!smem_set) {
        cudaFuncSetAttribute(gates_mma, cudaFuncAttributeMaxDynamicSharedMemorySize, SM_TOT);
        smem_set = 1;
    }

    dim3 blk(256);

    prep_weights<<<G4H_, 256>>>(Wih, Whh, bih, bhh);
    lane_kernel<<<1, 32>>>(lane, Wlg1, blg1, Wlg2, blg2);

    // embedding MLP; GEMM2 writes bf16 hi/lo permuted to [T][S][E]
    sgemm2<<<dim3(EH_ / BN, ST_ / BM), blk>>>(ST_, EH_, I_, inputData, I_, We1, be1,
                                              p_x1, EH_, FL_RELU | FL_SCALEA);
    sgemm2<<<dim3(E_ / BN, ST_ / BM), blk>>>(ST_, E_, EH_, p_x1, EH_, We2, be2,
                                             nullptr, E_, FL_RELU | FL_SPLIT);

    int ew = S_ * H_;
    zero_hc_kernel<<<(ew + 255) / 256, 256>>>();

    // recurrence: tensor-core (mma.sync) GEMM + fused cell, then maxpool(+split)
    dim3 ggrid(G4H_ / 128, S_ / 128);  // 16 x 32
    for (int t = 0; t < T_; t++) {
        gates_mma<<<ggrid, 128, SM_TOT>>>(t);
        maxpool_kernel<<<(ew + 255) / 256, 256>>>();
    }

    // output head (scalar GEMMs; small)
    sgemm2<<<dim3(O_ / BN, S_ / BM), blk>>>(S_, O_, H_, p_h, H_, Wout, bout,
                                            p_o1, O_, 0);
    sgemm2<<<dim3((F1_ + BN - 1) / BN, S_ / BM), blk>>>(S_, F1_, O_, p_o1, O_, Wf1, bf1,
                                                        p_o2, F1_, FL_RELU);
    sgemm2<<<dim3((F2_ + BN - 1) / BN, S_ / BM), blk>>>(S_, F2_, F1_, p_o2, F1_, Wf2, bf2,
                                                        p_o3, F2_, FL_RELU);
    head_final_kernel<<<S_, F2_>>>(Wf3, bf3, out);
    finalize_kernel<<<(ew + 255) / 256, 256>>>(out);
}

// round 6
// speedup vs baseline: 2.2727x; 1.1237x over previous
#include <cuda_runtime.h>
#include <cuda_bf16.h>
#include <math.h>
#include <cstdint>

typedef unsigned long long ull;

// Problem dims
#define S_   4096
#define T_   64
#define I_   64
#define EH_  128
#define E_   256
#define H_   512
#define O_   128
#define F1_  256
#define F2_  64
#define G4H_ (4*H_)       // 2048
#define KG_  (E_+H_)      // 768
#define ST_  (S_*T_)      // 262144

// ---------------- device scratch ----------------
__device__ float g_laneC;
__device__ float g_x1[(size_t)ST_ * EH_];               // 128 MB
__device__ __nv_bfloat16 g_xemb_hi[(size_t)ST_ * E_];   // [T][S][E] bf16 hi
__device__ __nv_bfloat16 g_xemb_lo[(size_t)ST_ * E_];   // [T][S][E] bf16 lo
__device__ __nv_bfloat16 g_Whi[(size_t)G4H_ * KG_];     // interleaved rows j*4+gate
__device__ __nv_bfloat16 g_Wlo[(size_t)G4H_ * KG_];
__device__ float g_bcomb[G4H_];
__device__ float g_h[(size_t)S_ * H_];
__device__ __nv_bfloat16 g_hhi[(size_t)S_ * H_];
__device__ __nv_bfloat16 g_hlo[(size_t)S_ * H_];
__device__ float g_hraw[(size_t)S_ * H_];
__device__ float g_c[(size_t)S_ * H_];
__device__ float g_o1[(size_t)S_ * O_];
__device__ float g_o2[(size_t)S_ * F1_];
__device__ float g_o3[(size_t)S_ * F2_];

// ---------------- helpers ----------------
__device__ __forceinline__ uint32_t smem_u32(const void* p) {
    uint32_t a;
    asm("{ .reg .u64 t; cvta.to.shared.u64 t, %1; cvt.u32.u64 %0, t; }" : "=r"(a) : "l"(p));
    return a;
}
#define CP16(dst, src) asm volatile("cp.async.cg.shared.global [%0], [%1], 16;" :: "r"(dst), "l"(src))
#define CP_COMMIT()    asm volatile("cp.async.commit_group;" ::: "memory")
#define CP_WAIT1()     asm volatile("cp.async.wait_group 1;" ::: "memory")
#define CP_WAIT0()     asm volatile("cp.async.wait_group 0;" ::: "memory")

#define MMA16816(c, a, b) \
    asm volatile("mma.sync.aligned.m16n8k16.row.col.f32.bf16.bf16.f32 " \
        "{%0,%1,%2,%3}, {%4,%5,%6,%7}, {%8,%9}, {%0,%1,%2,%3};" \
        : "+f"((c)[0]), "+f"((c)[1]), "+f"((c)[2]), "+f"((c)[3]) \
        : "r"((a)[0]), "r"((a)[1]), "r"((a)[2]), "r"((a)[3]), \
          "r"((b)[0]), "r"((b)[1]))

#define LDSM4(r0, r1, r2, r3, addr) \
    asm volatile("ldmatrix.sync.aligned.m8n8.x4.shared.b16 {%0,%1,%2,%3}, [%4];" \
        : "=r"(r0), "=r"(r1), "=r"(r2), "=r"(r3) : "r"(addr))

// packed f32x2 helpers for scalar GEMMs
#define FMA2(d, a, b) asm("fma.rn.f32x2 %0, %1, %2, %0;" : "+l"(d) : "l"(a), "l"(b))
#define PACK2(d, x)   asm("mov.b64 %0, {%1, %1};" : "=l"(d) : "f"(x))
__device__ __forceinline__ float2 unpk(ull v) {
    float2 r;
    asm("mov.b64 {%0, %1}, %2;" : "=f"(r.x), "=f"(r.y) : "l"(v));
    return r;
}
__device__ __forceinline__ float sigf(float x) { return __fdividef(1.0f, 1.0f + __expf(-x)); }
__device__ __forceinline__ float tanhf_(float x) {
    return 2.0f * __fdividef(1.0f, 1.0f + __expf(-2.0f * x)) - 1.0f;
}

// ---------------- lane gate ----------------
__global__ void lane_kernel(const float* __restrict__ lane,
                            const float* __restrict__ Wlg1,
                            const float* __restrict__ blg1,
                            const float* __restrict__ Wlg2,
                            const float* __restrict__ blg2) {
    int j = threadIdx.x;
    float lg = fmaxf(lane[0] * Wlg1[j] + blg1[j], 0.0f);
    float p = lg * Wlg2[j];
#pragma unroll
    for (int o = 16; o > 0; o >>= 1) p += __shfl_down_sync(0xFFFFFFFFu, p, o);
    if (j == 0) g_laneC = 1.0f / (1.0f + expf(-(p + blg2[0])));
}

// ---------------- weight interleave + bf16 split ----------------
__global__ void prep_weights(const float* __restrict__ Wih,
                             const float* __restrict__ Whh,
                             const float* __restrict__ bih,
                             const float* __restrict__ bhh) {
    int r = blockIdx.x;                 // interleaved row: j*4 + gate
    int orig = (r & 3) * H_ + (r >> 2);
    for (int k = threadIdx.x; k < KG_; k += blockDim.x) {
        float w = (k < E_) ? Wih[(size_t)orig * E_ + k] : Whh[(size_t)orig * H_ + (k - E_)];
        __nv_bfloat16 hi = __float2bfloat16(w);
        g_Whi[(size_t)r * KG_ + k] = hi;
        g_Wlo[(size_t)r * KG_ + k] = __float2bfloat16(w - __bfloat162float(hi));
    }
    if (threadIdx.x == 0) g_bcomb[r] = bih[orig] + bhh[orig];
}

// ---------------- scalar FFMA2 SGEMM (embedding + head) ----------------
#define BM 128
#define BN 128
#define BK 8
#define FL_RELU    1
#define FL_SCALEA  2
#define FL_SPLIT   4   // write bf16 hi/lo to g_xemb_* with [T][S][E] permute

__global__ __launch_bounds__(256, 2)
void sgemm2(int M, int N, int K,
            const float* __restrict__ A, int lda,
            const float* __restrict__ B,
            const float* __restrict__ bias,
            float* __restrict__ C, int ldc, int flags)
{
    __shared__ __align__(16) float As[BK][BM];
    __shared__ __align__(16) float Bs[BK][BN];

    const int tid = threadIdx.x;
    const int tx = tid & 15;
    const int ty = tid >> 4;
    const int bm = blockIdx.y * BM;
    const int bn = blockIdx.x * BN;
    const float scale = (flags & FL_SCALEA) ? g_laneC : 1.0f;
    const int lRow = tid >> 1;
    const int lCol = (tid & 1) * 4;

    ull acc[8][4];
#pragma unroll
    for (int i = 0; i < 8; i++)
#pragma unroll
        for (int p = 0; p < 4; p++) acc[i][p] = 0ull;

    for (int k0 = 0; k0 < K; k0 += BK) {
        float4 av = make_float4(0.f, 0.f, 0.f, 0.f);
        int ar = bm + lRow;
        if (ar < M) av = *reinterpret_cast<const float4*>(A + (size_t)ar * lda + (k0 + lCol));
        As[lCol + 0][lRow] = av.x * scale;
        As[lCol + 1][lRow] = av.y * scale;
        As[lCol + 2][lRow] = av.z * scale;
        As[lCol + 3][lRow] = av.w * scale;

        float4 bv = make_float4(0.f, 0.f, 0.f, 0.f);
        int br = bn + lRow;
        if (br < N) bv = *reinterpret_cast<const float4*>(B + (size_t)br * K + (k0 + lCol));
        Bs[lCol + 0][lRow] = bv.x;
        Bs[lCol + 1][lRow] = bv.y;
        Bs[lCol + 2][lRow] = bv.z;
        Bs[lCol + 3][lRow] = bv.w;

        __syncthreads();
#pragma unroll
        for (int k = 0; k < BK; k++) {
            float4 a0 = *reinterpret_cast<const float4*>(&As[k][ty * 4]);
            float4 a1 = *reinterpret_cast<const float4*>(&As[k][64 + ty * 4]);
            const ull* bp0 = reinterpret_cast<const ull*>(&Bs[k][tx * 4]);
            const ull* bp1 = reinterpret_cast<const ull*>(&Bs[k][64 + tx * 4]);
            ull b0 = bp0[0], b1 = bp0[1], b2 = bp1[0], b3 = bp1[1];
            float as[8] = {a0.x, a0.y, a0.z, a0.w, a1.x, a1.y, a1.z, a1.w};
            ull aa;
#pragma unroll
            for (int i = 0; i < 8; i++) {
                PACK2(aa, as[i]);
                FMA2(acc[i][0], aa, b0);
                FMA2(acc[i][1], aa, b1);
                FMA2(acc[i][2], aa, b2);
                FMA2(acc[i][3], aa, b3);
            }
        }
        __syncthreads();
    }

#pragma unroll
    for (int i = 0; i < 8; i++) {
        int row = bm + ((i < 4) ? (ty * 4 + i) : (64 + ty * 4 + (i - 4)));
        if (row >= M) continue;
        size_t orow = (flags & FL_SPLIT)
                      ? ((size_t)(row % T_) * S_ + (row / T_))
                      : (size_t)row;
#pragma unroll
        for (int p = 0; p < 4; p++) {
            float2 v = unpk(acc[i][p]);
            int c0 = bn + ((p < 2) ? (tx * 4 + p * 2) : (64 + tx * 4 + (p - 2) * 2));
#pragma unroll
            for (int q = 0; q < 2; q++) {
                int col = c0 + q;
                if (col >= N) continue;
                float val = (q == 0) ? v.x : v.y;
                if (bias) val += bias[col];
                if (flags & FL_RELU) val = fmaxf(val, 0.0f);
                if (flags & FL_SPLIT) {
                    __nv_bfloat16 hi = __float2bfloat16(val);
                    g_xemb_hi[orow * ldc + col] = hi;
                    g_xemb_lo[orow * ldc + col] = __float2bfloat16(val - __bfloat162float(hi));
                } else {
                    C[orow * ldc + col] = val;
                }
            }
        }
    }
}

// ============ mma.sync bf16 gates GEMM (K-extended 3-term split) + fused cell ============
// D[s, gatecol] over K'=2304: [A_hi|A_lo|A_hi] . [W_hi|W_hi|W_lo]
// CTA 128x128, 8 warps (32x64 warp tiles), BK=64, cp.async double buffer, ldmatrix.
#define GBK 64
#define NCH 36                 // 2304 / 64
#define KPAD 72                // 64 + 8 halves padding (row stride 144 B)
#define A_BYTES (128 * KPAD * 2)   // 18432
#define STAGE_B (2 * A_BYTES)      // 36864
#define SM_TOT  (2 * STAGE_B)      // 73728 (>= 128*132*4 epilogue staging)

__global__ __launch_bounds__(256, 2)
void gates_mma(int t)
{
    extern __shared__ char smem[];
    const uint32_t sb = smem_u32(smem);
    const int tid = threadIdx.x;
    const int lane = tid & 31;
    const int wid = tid >> 5;
    const int wm = wid & 3;        // 4 row-warps (32 rows each)
    const int wn = wid >> 2;       // 2 col-warps (64 cols each)
    const int bm = blockIdx.y * 128;
    const int bn = blockIdx.x * 128;

    float acc[2][8][4];
#pragma unroll
    for (int mf = 0; mf < 2; mf++)
#pragma unroll
        for (int nf = 0; nf < 8; nf++)
#pragma unroll
            for (int r = 0; r < 4; r++) acc[mf][nf][r] = 0.0f;

    auto load_chunk = [&](int ck, int st) {
        const int seg = ck / 12;          // 0: hi.hi  1: lo.hi  2: hi.lo
        const int kk = (ck % 12) * GBK;   // 0..704
        const __nv_bfloat16* asrc;
        size_t astr;
        if (kk < E_) {
            asrc = ((seg == 1) ? g_xemb_lo : g_xemb_hi) + ((size_t)t * S_ + bm) * E_ + kk;
            astr = E_;
        } else {
            asrc = ((seg == 1) ? g_hlo : g_hhi) + (size_t)bm * H_ + (kk - E_);
            astr = H_;
        }
        const __nv_bfloat16* bsrc = ((seg == 2) ? g_Wlo : g_Whi) + (size_t)bn * KG_ + kk;
        const uint32_t abase = sb + (uint32_t)(st * STAGE_B);
        const uint32_t bbase = abase + A_BYTES;
#pragma unroll
        for (int it = 0; it < 4; it++) {
            int i = tid + it * 256;
            int row = i >> 3, sg = i & 7;
            CP16(abase + row * 144 + sg * 16, asrc + (size_t)row * astr + sg * 8);
        }
#pragma unroll
        for (int it = 0; it < 4; it++) {
            int i = tid + it * 256;
            int row = i >> 3, sg = i & 7;
            CP16(bbase + row * 144 + sg * 16, bsrc + (size_t)row * KG_ + sg * 8);
        }
    };

    // per-lane ldmatrix address components
    const int grp = lane >> 3, lr = lane & 7;
    // A x4 groups: 0:(r+lr,k0) 1:(r+8+lr,k0) 2:(r+lr,k0+8) 3:(r+8+lr,k0+8)
    const int a_row = wm * 32 + (grp & 1) * 8 + lr;
    const int a_kh  = (grp >> 1) * 8;
    // B x4 groups: 0:(n+lr,k0) 1:(n+lr,k0+8) 2:(n+8+lr,k0) 3:(n+8+lr,k0+8)
    const int b_row = wn * 64 + (grp >> 1) * 8 + lr;
    const int b_kh  = (grp & 1) * 8;

    load_chunk(0, 0);
    CP_COMMIT();

    for (int ck = 0; ck < NCH; ck++) {
        const int st = ck & 1;
        if (ck + 1 < NCH) {
            load_chunk(ck + 1, st ^ 1);
            CP_COMMIT();
            CP_WAIT1();
        } else {
            CP_WAIT0();
        }
        __syncthreads();

        const uint32_t abase = sb + (uint32_t)(st * STAGE_B);
        const uint32_t bbase = abase + A_BYTES;
#pragma unroll
        for (int kh = 0; kh < 4; kh++) {
            const int k0 = kh * 16;
            uint32_t af[2][4];
#pragma unroll
            for (int mf = 0; mf < 2; mf++)
                LDSM4(af[mf][0], af[mf][1], af[mf][2], af[mf][3],
                      abase + (uint32_t)((a_row + mf * 16) * 144 + (k0 + a_kh) * 2));
            uint32_t bf[8][2];
#pragma unroll
            for (int q = 0; q < 4; q++) {
                uint32_t r0, r1, r2, r3;
                LDSM4(r0, r1, r2, r3,
                      bbase + (uint32_t)((b_row + q * 16) * 144 + (k0 + b_kh) * 2));
                bf[2 * q][0] = r0; bf[2 * q][1] = r1;
                bf[2 * q + 1][0] = r2; bf[2 * q + 1][1] = r3;
            }
#pragma unroll
            for (int mf = 0; mf < 2; mf++)
#pragma unroll
                for (int nf = 0; nf < 8; nf++)
                    MMA16816(acc[mf][nf], af[mf], bf[nf]);
        }
        __syncthreads();
    }

    // ---- epilogue: stage accum to smem, then fused LSTM cell ----
    float* Sg = reinterpret_cast<float*>(smem);  // [128][132]
#pragma unroll
    for (int mf = 0; mf < 2; mf++) {
        int r0 = wm * 32 + mf * 16 + (lane >> 2);
#pragma unroll
        for (int nf = 0; nf < 8; nf++) {
            int col = wn * 64 + nf * 8 + (lane & 3) * 2;
            *reinterpret_cast<float2*>(&Sg[r0 * 132 + col]) =
                make_float2(acc[mf][nf][0], acc[mf][nf][1]);
            *reinterpret_cast<float2*>(&Sg[(r0 + 8) * 132 + col]) =
                make_float2(acc[mf][nf][2], acc[mf][nf][3]);
        }
    }
    __syncthreads();

    const int jbase = bn >> 2;   // first h-unit of this tile
#pragma unroll 4
    for (int it = 0; it < 16; it++) {
        int idx = tid + it * 256;
        int row = idx >> 5, u = idx & 31;
        float4 gv = *reinterpret_cast<const float4*>(&Sg[row * 132 + u * 4]);
        float4 bb = *reinterpret_cast<const float4*>(&g_bcomb[bn + u * 4]);
        size_t cidx = (size_t)(bm + row) * H_ + (jbase + u);
        float cn = sigf(gv.y + bb.y) * g_c[cidx] + sigf(gv.x + bb.x) * tanhf_(gv.z + bb.z);
        g_c[cidx] = cn;
        g_hraw[cidx] = sigf(gv.w + bb.w) * tanhf_(cn);
    }
}

// ---------------- spatial maxpool + bf16 split of h ----------------
__global__ void maxpool_kernel() {
    int idx = blockIdx.x * blockDim.x + threadIdx.x;
    if (idx >= S_ * H_) return;
    int s = idx >> 9;
    float v = g_hraw[idx];
    if (s > 0)       v = fmaxf(v, g_hraw[idx - H_]);
    if (s < S_ - 1)  v = fmaxf(v, g_hraw[idx + H_]);
    g_h[idx] = v;
    __nv_bfloat16 hi = __float2bfloat16(v);
    g_hhi[idx] = hi;
    g_hlo[idx] = __float2bfloat16(v - __bfloat162float(hi));
}

__global__ void zero_hc_kernel() {
    int idx = blockIdx.x * blockDim.x + threadIdx.x;
    if (idx >= S_ * H_) return;
    g_h[idx] = 0.0f;
    g_c[idx] = 0.0f;
    g_hhi[idx] = __float2bfloat16(0.0f);
    g_hlo[idx] = __float2bfloat16(0.0f);
}

// ---------------- final head ----------------
__global__ void head_final_kernel(const float* __restrict__ Wf3,
                                  const float* __restrict__ bf3,
                                  float* __restrict__ out) {
    __shared__ float red[F2_];
    int s = blockIdx.x;
    int t = threadIdx.x;
    red[t] = g_o3[(size_t)s * F2_ + t] * Wf3[t];
    __syncthreads();
#pragma unroll
    for (int o = 32; o > 0; o >>= 1) {
        if (t < o) red[t] += red[t + o];
        __syncthreads();
    }
    if (t == 0) out[s] = (red[0] + bf3[0]) / g_laneC;
}

__global__ void finalize_kernel(float* __restrict__ out) {
    int idx = blockIdx.x * blockDim.x + threadIdx.x;
    if (idx >= S_ * H_) return;
    out[S_ + idx] = g_h[idx];
    out[S_ + (size_t)S_ * H_ + idx] = g_c[idx];
}

// ---------------- host launcher ----------------
extern "C" void kernel_launch(void* const* d_in, const int* in_sizes, int n_in,
                              void* d_out, int out_size) {
    const float* inputData = (const float*)d_in[0];
    const float* lane      = (const float*)d_in[1];
    const float* Wlg1      = (const float*)d_in[2];
    const float* blg1      = (const float*)d_in[3];
    const float* Wlg2      = (const float*)d_in[4];
    const float* blg2      = (const float*)d_in[5];
    const float* We1       = (const float*)d_in[6];
    const float* be1       = (const float*)d_in[7];
    const float* We2       = (const float*)d_in[8];
    const float* be2       = (const float*)d_in[9];
    const float* Wih       = (const float*)d_in[10];
    const float* bih       = (const float*)d_in[11];
    const float* Whh       = (const float*)d_in[12];
    const float* bhh       = (const float*)d_in[13];
    const float* Wout      = (const float*)d_in[14];
    const float* bout      = (const float*)d_in[15];
    const float* Wf1       = (const float*)d_in[16];
    const float* bf1       = (const float*)d_in[17];
    const float* Wf2       = (const float*)d_in[18];
    const float* bf2       = (const float*)d_in[19];
    const float* Wf3       = (const float*)d_in[20];
    const float* bf3       = (const float*)d_in[21];
    float* out = (float*)d_out;

    float *p_x1, *p_h, *p_o1, *p_o2, *p_o3;
    cudaGetSymbolAddress((void**)&p_x1, g_x1);
    cudaGetSymbolAddress((void**)&p_h,  g_h);
    cudaGetSymbolAddress((void**)&p_o1, g_o1);
    cudaGetSymbolAddress((void**)&p_o2, g_o2);
    cudaGetSymbolAddress((void**)&p_o3, g_o3);

    static int smem_set = 0;
    if (!smem_set) {
        cudaFuncSetAttribute(gates_mma, cudaFuncAttributeMaxDynamicSharedMemorySize, SM_TOT);
        smem_set = 1;
    }

    dim3 blk(256);

    prep_weights<<<G4H_, 256>>>(Wih, Whh, bih, bhh);
    lane_kernel<<<1, 32>>>(lane, Wlg1, blg1, Wlg2, blg2);

    // embedding MLP; GEMM2 writes bf16 hi/lo permuted to [T][S][E]
    sgemm2<<<dim3(EH_ / BN, ST_ / BM), blk>>>(ST_, EH_, I_, inputData, I_, We1, be1,
                                              p_x1, EH_, FL_RELU | FL_SCALEA);
    sgemm2<<<dim3(E_ / BN, ST_ / BM), blk>>>(ST_, E_, EH_, p_x1, EH_, We2, be2,
                                             nullptr, E_, FL_RELU | FL_SPLIT);

    int ew = S_ * H_;
    zero_hc_kernel<<<(ew + 255) / 256, 256>>>();

    // recurrence: tensor-core (mma.sync + ldmatrix) GEMM + fused cell, then maxpool
    dim3 ggrid(G4H_ / 128, S_ / 128);  // 16 x 32
    for (int t = 0; t < T_; t++) {
        gates_mma<<<ggrid, 256, SM_TOT>>>(t);
        maxpool_kernel<<<(ew + 255) / 256, 256>>>();
    }

    // output head (scalar GEMMs; small)
    sgemm2<<<dim3(O_ / BN, S_ / BM), blk>>>(S_, O_, H_, p_h, H_, Wout, bout,
                                            p_o1, O_, 0);
    sgemm2<<<dim3((F1_ + BN - 1) / BN, S_ / BM), blk>>>(S_, F1_, O_, p_o1, O_, Wf1, bf1,
                                                        p_o2, F1_, FL_RELU);
    sgemm2<<<dim3((F2_ + BN - 1) / BN, S_ / BM), blk>>>(S_, F2_, F1_, p_o2, F1_, Wf2, bf2,
                                                        p_o3, F2_, FL_RELU);
    head_final_kernel<<<S_, F2_>>>(Wf3, bf3, out);
    finalize_kernel<<<(ew + 255) / 256, 256>>>(out);
}

// round 7
// speedup vs baseline: 2.3729x; 1.0441x over previous
#include <cuda_runtime.h>
#include <cuda_bf16.h>
#include <math.h>
#include <cstdint>

typedef unsigned long long ull;

// Problem dims
#define S_   4096
#define T_   64
#define I_   64
#define EH_  128
#define E_   256
#define H_   512
#define O_   128
#define F1_  256
#define F2_  64
#define G4H_ (4*H_)       // 2048
#define KG_  (E_+H_)      // 768
#define KX_  (3*KG_)      // 2304  (K-extended 3-term split)
#define NK16 (KX_/16)     // 144
#define NN16 (G4H_/16)    // 128
#define ST_  (S_*T_)      // 262144

// ---------------- device scratch ----------------
__device__ float g_laneC;
__device__ float g_x1[(size_t)ST_ * EH_];               // 128 MB
__device__ __nv_bfloat16 g_xemb_hi[(size_t)ST_ * E_];   // [T][S][E] bf16 hi
__device__ __nv_bfloat16 g_xemb_lo[(size_t)ST_ * E_];   // [T][S][E] bf16 lo
__device__ uint4 g_Bfrag[(size_t)NK16 * NN16 * 32];     // 9.4 MB, mma fragment layout
__device__ float g_bcomb[G4H_];
__device__ float g_h[(size_t)S_ * H_];
__device__ __nv_bfloat16 g_hhi[(size_t)S_ * H_];
__device__ __nv_bfloat16 g_hlo[(size_t)S_ * H_];
__device__ float g_hraw[(size_t)S_ * H_];
__device__ float g_c[(size_t)S_ * H_];
__device__ float g_o1[(size_t)S_ * O_];
__device__ float g_o2[(size_t)S_ * F1_];
__device__ float g_o3[(size_t)S_ * F2_];

// ---------------- helpers ----------------
__device__ __forceinline__ uint32_t smem_u32(const void* p) {
    uint32_t a;
    asm("{ .reg .u64 t; cvta.to.shared.u64 t, %1; cvt.u32.u64 %0, t; }" : "=r"(a) : "l"(p));
    return a;
}
#define CP16(dst, src) asm volatile("cp.async.cg.shared.global [%0], [%1], 16;" :: "r"(dst), "l"(src))
#define CP_COMMIT()    asm volatile("cp.async.commit_group;" ::: "memory")
#define CP_WAIT1()     asm volatile("cp.async.wait_group 1;" ::: "memory")
#define CP_WAIT0()     asm volatile("cp.async.wait_group 0;" ::: "memory")

#define MMA16816(c, a, b) \
    asm volatile("mma.sync.aligned.m16n8k16.row.col.f32.bf16.bf16.f32 " \
        "{%0,%1,%2,%3}, {%4,%5,%6,%7}, {%8,%9}, {%0,%1,%2,%3};" \
        : "+f"((c)[0]), "+f"((c)[1]), "+f"((c)[2]), "+f"((c)[3]) \
        : "r"((a)[0]), "r"((a)[1]), "r"((a)[2]), "r"((a)[3]), \
          "r"((b)[0]), "r"((b)[1]))

#define LDSM4(r0, r1, r2, r3, addr) \
    asm volatile("ldmatrix.sync.aligned.m8n8.x4.shared.b16 {%0,%1,%2,%3}, [%4];" \
        : "=r"(r0), "=r"(r1), "=r"(r2), "=r"(r3) : "r"(addr))

// packed f32x2 helpers for scalar GEMMs
#define FMA2(d, a, b) asm("fma.rn.f32x2 %0, %1, %2, %0;" : "+l"(d) : "l"(a), "l"(b))
#define PACK2(d, x)   asm("mov.b64 %0, {%1, %1};" : "=l"(d) : "f"(x))
__device__ __forceinline__ float2 unpk(ull v) {
    float2 r;
    asm("mov.b64 {%0, %1}, %2;" : "=f"(r.x), "=f"(r.y) : "l"(v));
    return r;
}
__device__ __forceinline__ float sigf(float x) { return __fdividef(1.0f, 1.0f + __expf(-x)); }
__device__ __forceinline__ float tanhf_(float x) {
    return 2.0f * __fdividef(1.0f, 1.0f + __expf(-2.0f * x)) - 1.0f;
}

// ---------------- lane gate ----------------
__global__ void lane_kernel(const float* __restrict__ lane,
                            const float* __restrict__ Wlg1,
                            const float* __restrict__ blg1,
                            const float* __restrict__ Wlg2,
                            const float* __restrict__ blg2) {
    int j = threadIdx.x;
    float lg = fmaxf(lane[0] * Wlg1[j] + blg1[j], 0.0f);
    float p = lg * Wlg2[j];
#pragma unroll
    for (int o = 16; o > 0; o >>= 1) p += __shfl_down_sync(0xFFFFFFFFu, p, o);
    if (j == 0) g_laneC = 1.0f / (1.0f + expf(-(p + blg2[0])));
}

// ---------------- combined bias ----------------
__global__ void prep_bias(const float* __restrict__ bih, const float* __restrict__ bhh) {
    int r = blockIdx.x * blockDim.x + threadIdx.x;
    if (r >= G4H_) return;
    int orig = (r & 3) * H_ + (r >> 2);       // interleaved row: j*4 + gate
    g_bcomb[r] = bih[orig] + bhh[orig];
}

// ---------------- weights -> mma B-fragment layout (hi/hi/lo over K') ----------------
// g_Bfrag[(k16*NN16 + n16)*32 + ln] = {j0..j3}:
//   j bit0 -> k-offset 8 (b-reg index), bit1 -> n8 sub-tile
//   value u32 = bf16x2( W'[n][kp], W'[n][kp+1] ), n = n16*16+(j>>1)*8+(ln>>2),
//   kp = k16*16+(j&1)*8+(ln&3)*2;  seg = kp/768 (0,1: hi; 2: lo), k = kp%768
__device__ __forceinline__ uint16_t convW(const float* Wih, const float* Whh,
                                          int n, int k, int seg) {
    int orig = (n & 3) * H_ + (n >> 2);
    float w = (k < E_) ? Wih[(size_t)orig * E_ + k] : Whh[(size_t)orig * H_ + (k - E_)];
    __nv_bfloat16 hi = __float2bfloat16(w);
    __nv_bfloat16 v = (seg < 2) ? hi : __float2bfloat16(w - __bfloat162float(hi));
    return *reinterpret_cast<uint16_t*>(&v);
}

__global__ void prep_bfrag(const float* __restrict__ Wih, const float* __restrict__ Whh) {
    int k16 = blockIdx.x;   // 0..143
    int n16 = blockIdx.y;   // 0..127
    int ln = threadIdx.x;   // 0..31
    uint32_t vals[4];
#pragma unroll
    for (int j = 0; j < 4; j++) {
        int n = n16 * 16 + ((j >> 1) * 8) + (ln >> 2);
        int kp = k16 * 16 + ((j & 1) * 8) + (ln & 3) * 2;
        int seg = kp / KG_;
        int k = kp - seg * KG_;
        uint16_t v0 = convW(Wih, Whh, n, k, seg);
        uint16_t v1 = convW(Wih, Whh, n, k + 1, seg);
        vals[j] = (uint32_t)v0 | ((uint32_t)v1 << 16);
    }
    g_Bfrag[((size_t)k16 * NN16 + n16) * 32 + ln] =
        make_uint4(vals[0], vals[1], vals[2], vals[3]);
}

// ---------------- scalar FFMA2 SGEMM (embedding + head) ----------------
#define BM 128
#define BN 128
#define BK 8
#define FL_RELU    1
#define FL_SCALEA  2
#define FL_SPLIT   4   // write bf16 hi/lo to g_xemb_* with [T][S][E] permute

__global__ __launch_bounds__(256, 2)
void sgemm2(int M, int N, int K,
            const float* __restrict__ A, int lda,
            const float* __restrict__ B,
            const float* __restrict__ bias,
            float* __restrict__ C, int ldc, int flags)
{
    __shared__ __align__(16) float As[BK][BM];
    __shared__ __align__(16) float Bs[BK][BN];

    const int tid = threadIdx.x;
    const int tx = tid & 15;
    const int ty = tid >> 4;
    const int bm = blockIdx.y * BM;
    const int bn = blockIdx.x * BN;
    const float scale = (flags & FL_SCALEA) ? g_laneC : 1.0f;
    const int lRow = tid >> 1;
    const int lCol = (tid & 1) * 4;

    ull acc[8][4];
#pragma unroll
    for (int i = 0; i < 8; i++)
#pragma unroll
        for (int p = 0; p < 4; p++) acc[i][p] = 0ull;

    for (int k0 = 0; k0 < K; k0 += BK) {
        float4 av = make_float4(0.f, 0.f, 0.f, 0.f);
        int ar = bm + lRow;
        if (ar < M) av = *reinterpret_cast<const float4*>(A + (size_t)ar * lda + (k0 + lCol));
        As[lCol + 0][lRow] = av.x * scale;
        As[lCol + 1][lRow] = av.y * scale;
        As[lCol + 2][lRow] = av.z * scale;
        As[lCol + 3][lRow] = av.w * scale;

        float4 bv = make_float4(0.f, 0.f, 0.f, 0.f);
        int br = bn + lRow;
        if (br < N) bv = *reinterpret_cast<const float4*>(B + (size_t)br * K + (k0 + lCol));
        Bs[lCol + 0][lRow] = bv.x;
        Bs[lCol + 1][lRow] = bv.y;
        Bs[lCol + 2][lRow] = bv.z;
        Bs[lCol + 3][lRow] = bv.w;

        __syncthreads();
#pragma unroll
        for (int k = 0; k < BK; k++) {
            float4 a0 = *reinterpret_cast<const float4*>(&As[k][ty * 4]);
            float4 a1 = *reinterpret_cast<const float4*>(&As[k][64 + ty * 4]);
            const ull* bp0 = reinterpret_cast<const ull*>(&Bs[k][tx * 4]);
            const ull* bp1 = reinterpret_cast<const ull*>(&Bs[k][64 + tx * 4]);
            ull b0 = bp0[0], b1 = bp0[1], b2 = bp1[0], b3 = bp1[1];
            float as[8] = {a0.x, a0.y, a0.z, a0.w, a1.x, a1.y, a1.z, a1.w};
            ull aa;
#pragma unroll
            for (int i = 0; i < 8; i++) {
                PACK2(aa, as[i]);
                FMA2(acc[i][0], aa, b0);
                FMA2(acc[i][1], aa, b1);
                FMA2(acc[i][2], aa, b2);
                FMA2(acc[i][3], aa, b3);
            }
        }
        __syncthreads();
    }

#pragma unroll
    for (int i = 0; i < 8; i++) {
        int row = bm + ((i < 4) ? (ty * 4 + i) : (64 + ty * 4 + (i - 4)));
        if (row >= M) continue;
        size_t orow = (flags & FL_SPLIT)
                      ? ((size_t)(row % T_) * S_ + (row / T_))
                      : (size_t)row;
#pragma unroll
        for (int p = 0; p < 4; p++) {
            float2 v = unpk(acc[i][p]);
            int c0 = bn + ((p < 2) ? (tx * 4 + p * 2) : (64 + tx * 4 + (p - 2) * 2));
#pragma unroll
            for (int q = 0; q < 2; q++) {
                int col = c0 + q;
                if (col >= N) continue;
                float val = (q == 0) ? v.x : v.y;
                if (bias) val += bias[col];
                if (flags & FL_RELU) val = fmaxf(val, 0.0f);
                if (flags & FL_SPLIT) {
                    __nv_bfloat16 hi = __float2bfloat16(val);
                    g_xemb_hi[orow * ldc + col] = hi;
                    g_xemb_lo[orow * ldc + col] = __float2bfloat16(val - __bfloat162float(hi));
                } else {
                    C[orow * ldc + col] = val;
                }
            }
        }
    }
}

// ============ mma.sync gates GEMM: A via smem/LDSM, B direct from L2 fragments ============
// CTA 128x128, 8 warps (32x64 warp tiles), BK=64 (4 k16 per chunk), 36 chunks.
#define GBK 64
#define NCH 36
#define KPAD 72                    // A row stride 144 B (LDSM conflict-free)
#define A_BYTES (128 * KPAD * 2)   // 18432 per stage
#define SM_TOT  (128 * 132 * 4)    // 67584 (epilogue staging; > 2*A_BYTES)

__global__ __launch_bounds__(256, 2)
void gates_mma(int t)
{
    extern __shared__ char smem[];
    const uint32_t sb = smem_u32(smem);
    const int tid = threadIdx.x;
    const int lane = tid & 31;
    const int wid = tid >> 5;
    const int wm = wid & 3;        // 4 row-warps (32 rows each)
    const int wn = wid >> 2;       // 2 col-warps (64 cols each)
    const int bm = blockIdx.y * 128;
    const int bn = blockIdx.x * 128;
    const int n16b = blockIdx.x * 8 + wn * 4;   // first n16 block for this warp

    float acc[2][8][4];
#pragma unroll
    for (int mf = 0; mf < 2; mf++)
#pragma unroll
        for (int nf = 0; nf < 8; nf++)
#pragma unroll
            for (int r = 0; r < 4; r++) acc[mf][nf][r] = 0.0f;

    // A chunk loader (smem double buffer)
    auto load_chunk = [&](int ck, int st) {
        const int seg = ck / 12;          // 0: hi  1: lo  2: hi
        const int kk = (ck % 12) * GBK;
        const __nv_bfloat16* asrc;
        size_t astr;
        if (kk < E_) {
            asrc = ((seg == 1) ? g_xemb_lo : g_xemb_hi) + ((size_t)t * S_ + bm) * E_ + kk;
            astr = E_;
        } else {
            asrc = ((seg == 1) ? g_hlo : g_hhi) + (size_t)bm * H_ + (kk - E_);
            astr = H_;
        }
        const uint32_t abase = sb + (uint32_t)(st * A_BYTES);
#pragma unroll
        for (int it = 0; it < 4; it++) {
            int i = tid + it * 256;
            int row = i >> 3, sg = i & 7;
            CP16(abase + row * 144 + sg * 16, asrc + (size_t)row * astr + sg * 8);
        }
    };

    // per-lane A ldmatrix addressing
    const int grp = lane >> 3, lr = lane & 7;
    const int a_row = wm * 32 + (grp & 1) * 8 + lr;
    const int a_kh  = (grp >> 1) * 8;

    // B fragment pointer for this lane
    const uint4* __restrict__ bfp = g_Bfrag + lane;

    load_chunk(0, 0);
    CP_COMMIT();

    for (int ck = 0; ck < NCH; ck++) {
        const int st = ck & 1;
        if (ck + 1 < NCH) {
            load_chunk(ck + 1, st ^ 1);
            CP_COMMIT();
            CP_WAIT1();
        } else {
            CP_WAIT0();
        }
        __syncthreads();

        const uint32_t abase = sb + (uint32_t)(st * A_BYTES);
        const int k16base = ck * 4;

        // prime B for kh=0
        uint4 bv[4];
#pragma unroll
        for (int q = 0; q < 4; q++)
            bv[q] = __ldg(bfp + ((size_t)k16base * NN16 + (n16b + q)) * 32);

#pragma unroll
        for (int kh = 0; kh < 4; kh++) {
            uint4 bnx[4];
            if (kh < 3) {
#pragma unroll
                for (int q = 0; q < 4; q++)
                    bnx[q] = __ldg(bfp + ((size_t)(k16base + kh + 1) * NN16 + (n16b + q)) * 32);
            }
            const int k0 = kh * 16;
            uint32_t af[2][4];
#pragma unroll
            for (int mf = 0; mf < 2; mf++)
                LDSM4(af[mf][0], af[mf][1], af[mf][2], af[mf][3],
                      abase + (uint32_t)((a_row + mf * 16) * 144 + (k0 + a_kh) * 2));
            uint32_t bf[8][2];
#pragma unroll
            for (int q = 0; q < 4; q++) {
                bf[2 * q][0] = bv[q].x;     // n8 even, k+0
                bf[2 * q][1] = bv[q].y;     // n8 even, k+8
                bf[2 * q + 1][0] = bv[q].z; // n8 odd,  k+0
                bf[2 * q + 1][1] = bv[q].w; // n8 odd,  k+8
            }
#pragma unroll
            for (int mf = 0; mf < 2; mf++)
#pragma unroll
                for (int nf = 0; nf < 8; nf++)
                    MMA16816(acc[mf][nf], af[mf], bf[nf]);
#pragma unroll
            for (int q = 0; q < 4; q++) bv[q] = bnx[q];
        }
        __syncthreads();
    }

    // ---- epilogue: stage accum to smem, then fused LSTM cell ----
    float* Sg = reinterpret_cast<float*>(smem);  // [128][132]
#pragma unroll
    for (int mf = 0; mf < 2; mf++) {
        int r0 = wm * 32 + mf * 16 + (lane >> 2);
#pragma unroll
        for (int nf = 0; nf < 8; nf++) {
            int col = wn * 64 + nf * 8 + (lane & 3) * 2;
            *reinterpret_cast<float2*>(&Sg[r0 * 132 + col]) =
                make_float2(acc[mf][nf][0], acc[mf][nf][1]);
            *reinterpret_cast<float2*>(&Sg[(r0 + 8) * 132 + col]) =
                make_float2(acc[mf][nf][2], acc[mf][nf][3]);
        }
    }
    __syncthreads();

    const int jbase = bn >> 2;   // first h-unit of this tile
#pragma unroll 4
    for (int it = 0; it < 16; it++) {
        int idx = tid + it * 256;
        int row = idx >> 5, u = idx & 31;
        float4 gv = *reinterpret_cast<const float4*>(&Sg[row * 132 + u * 4]);
        float4 bb = *reinterpret_cast<const float4*>(&g_bcomb[bn + u * 4]);
        size_t cidx = (size_t)(bm + row) * H_ + (jbase + u);
        float cn = sigf(gv.y + bb.y) * g_c[cidx] + sigf(gv.x + bb.x) * tanhf_(gv.z + bb.z);
        g_c[cidx] = cn;
        g_hraw[cidx] = sigf(gv.w + bb.w) * tanhf_(cn);
    }
}

// ---------------- spatial maxpool + bf16 split of h ----------------
__global__ void maxpool_kernel() {
    int idx = blockIdx.x * blockDim.x + threadIdx.x;
    if (idx >= S_ * H_) return;
    int s = idx >> 9;
    float v = g_hraw[idx];
    if (s > 0)       v = fmaxf(v, g_hraw[idx - H_]);
    if (s < S_ - 1)  v = fmaxf(v, g_hraw[idx + H_]);
    g_h[idx] = v;
    __nv_bfloat16 hi = __float2bfloat16(v);
    g_hhi[idx] = hi;
    g_hlo[idx] = __float2bfloat16(v - __bfloat162float(hi));
}

__global__ void zero_hc_kernel() {
    int idx = blockIdx.x * blockDim.x + threadIdx.x;
    if (idx >= S_ * H_) return;
    g_h[idx] = 0.0f;
    g_c[idx] = 0.0f;
    g_hhi[idx] = __float2bfloat16(0.0f);
    g_hlo[idx] = __float2bfloat16(0.0f);
}

// ---------------- final head ----------------
__global__ void head_final_kernel(const float* __restrict__ Wf3,
                                  const float* __restrict__ bf3,
                                  float* __restrict__ out) {
    __shared__ float red[F2_];
    int s = blockIdx.x;
    int t = threadIdx.x;
    red[t] = g_o3[(size_t)s * F2_ + t] * Wf3[t];
    __syncthreads();
#pragma unroll
    for (int o = 32; o > 0; o >>= 1) {
        if (t < o) red[t] += red[t + o];
        __syncthreads();
    }
    if (t == 0) out[s] = (red[0] + bf3[0]) / g_laneC;
}

__global__ void finalize_kernel(float* __restrict__ out) {
    int idx = blockIdx.x * blockDim.x + threadIdx.x;
    if (idx >= S_ * H_) return;
    out[S_ + idx] = g_h[idx];
    out[S_ + (size_t)S_ * H_ + idx] = g_c[idx];
}

// ---------------- host launcher ----------------
extern "C" void kernel_launch(void* const* d_in, const int* in_sizes, int n_in,
                              void* d_out, int out_size) {
    const float* inputData = (const float*)d_in[0];
    const float* lane      = (const float*)d_in[1];
    const float* Wlg1      = (const float*)d_in[2];
    const float* blg1      = (const float*)d_in[3];
    const float* Wlg2      = (const float*)d_in[4];
    const float* blg2      = (const float*)d_in[5];
    const float* We1       = (const float*)d_in[6];
    const float* be1       = (const float*)d_in[7];
    const float* We2       = (const float*)d_in[8];
    const float* be2       = (const float*)d_in[9];
    const float* Wih       = (const float*)d_in[10];
    const float* bih       = (const float*)d_in[11];
    const float* Whh       = (const float*)d_in[12];
    const float* bhh       = (const float*)d_in[13];
    const float* Wout      = (const float*)d_in[14];
    const float* bout      = (const float*)d_in[15];
    const float* Wf1       = (const float*)d_in[16];
    const float* bf1       = (const float*)d_in[17];
    const float* Wf2       = (const float*)d_in[18];
    const float* bf2       = (const float*)d_in[19];
    const float* Wf3       = (const float*)d_in[20];
    const float* bf3       = (const float*)d_in[21];
    float* out = (float*)d_out;

    float *p_x1, *p_h, *p_o1, *p_o2, *p_o3;
    cudaGetSymbolAddress((void**)&p_x1, g_x1);
    cudaGetSymbolAddress((void**)&p_h,  g_h);
    cudaGetSymbolAddress((void**)&p_o1, g_o1);
    cudaGetSymbolAddress((void**)&p_o2, g_o2);
    cudaGetSymbolAddress((void**)&p_o3, g_o3);

    static int smem_set = 0;
    if (!smem_set) {
        cudaFuncSetAttribute(gates_mma, cudaFuncAttributeMaxDynamicSharedMemorySize, SM_TOT);
        smem_set = 1;
    }

    dim3 blk(256);

    prep_bias<<<(G4H_ + 255) / 256, 256>>>(bih, bhh);
    prep_bfrag<<<dim3(NK16, NN16), 32>>>(Wih, Whh);
    lane_kernel<<<1, 32>>>(lane, Wlg1, blg1, Wlg2, blg2);

    // embedding MLP; GEMM2 writes bf16 hi/lo permuted to [T][S][E]
    sgemm2<<<dim3(EH_ / BN, ST_ / BM), blk>>>(ST_, EH_, I_, inputData, I_, We1, be1,
                                              p_x1, EH_, FL_RELU | FL_SCALEA);
    sgemm2<<<dim3(E_ / BN, ST_ / BM), blk>>>(ST_, E_, EH_, p_x1, EH_, We2, be2,
                                             nullptr, E_, FL_RELU | FL_SPLIT);

    int ew = S_ * H_;
    zero_hc_kernel<<<(ew + 255) / 256, 256>>>();

    // recurrence
    dim3 ggrid(G4H_ / 128, S_ / 128);  // 16 x 32
    for (int t = 0; t < T_; t++) {
        gates_mma<<<ggrid, 256, SM_TOT>>>(t);
        maxpool_kernel<<<(ew + 255) / 256, 256>>>();
    }

    // output head (scalar GEMMs; small)
    sgemm2<<<dim3(O_ / BN, S_ / BM), blk>>>(S_, O_, H_, p_h, H_, Wout, bout,
                                            p_o1, O_, 0);
    sgemm2<<<dim3((F1_ + BN - 1) / BN, S_ / BM), blk>>>(S_, F1_, O_, p_o1, O_, Wf1, bf1,
                                                        p_o2, F1_, FL_RELU);
    sgemm2<<<dim3((F2_ + BN - 1) / BN, S_ / BM), blk>>>(S_, F2_, F1_, p_o2, F1_, Wf2, bf2,
                                                        p_o3, F2_, FL_RELU);
    head_final_kernel<<<S_, F2_>>>(Wf3, bf3, out);
    finalize_kernel<<<(ew + 255) / 256, 256>>>(out);
}